// round 15
// baseline (speedup 1.0000x reference)
#include <cuda_runtime.h>
#include <cuda_fp16.h>
#include <mma.h>
#include <math.h>

using namespace nvcuda;

#define NMAX 100000
#define EMAX 1600000
#define CIN  64

// ---------------- device scratch (no allocation allowed) ----------------
__device__ int   g_is64;
__device__ int   g_esrc[EMAX];          // CSR: src ids sorted by dst
__device__ int   g_cnt[NMAX];
__device__ int   g_scan[NMAX];
__device__ int   g_bsum[512];
__device__ int   g_rowstart[NMAX + 1];
__device__ int   g_cur[NMAX];
__device__ float g_inv[NMAX];
__device__ __align__(256) __half g_ylh[(size_t)NMAX * 64];   // fp16 gather payload
__device__ __align__(256) float  g_yr[(size_t)NMAX * 64];
__device__ __align__(256) float  g_h0[(size_t)NMAX * 64];
__device__ __align__(256) float  g_h1[(size_t)NMAX * 64];
// pre-split combined weights [Wl|Wr], fp16 hi + lo, row-major [k][c]
__device__ __align__(256) __half g_w0h[CIN * 128];
__device__ __align__(256) __half g_w0l[CIN * 128];
__device__ __align__(256) __half g_w1h[CIN * 128];
__device__ __align__(256) __half g_w1l[CIN * 128];
__device__ __align__(256) __half g_w2h[CIN * 80];
__device__ __align__(256) __half g_w2l[CIN * 80];
__device__ float g_stats0[128];         // layer0 [sum(64) | sumsq(64)]
__device__ float g_stats1[128];         // layer1
__device__ int   g_arr0;                // arrival counters (last-block bn finalize)
__device__ int   g_arr1;
__device__ float g_aff0[128];           // [scale | shift]
__device__ float g_aff1[128];

// ---------------- zero + dtype detect (block 1) ----------------
__global__ void k_zero(const unsigned int* __restrict__ w, int N) {
    int i = blockIdx.x * 256 + threadIdx.x;
    if (i < N) g_cnt[i] = 0;
    if (blockIdx.x == 0) {
        if (threadIdx.x < 128) { g_stats0[threadIdx.x] = 0.0f; g_stats1[threadIdx.x] = 0.0f; }
        if (threadIdx.x == 0) { g_arr0 = 0; g_arr1 = 0; }
    } else if (blockIdx.x == 1) {
        int ok = 1;
#pragma unroll
        for (int r = 0; r < 8; r++) {
            int q = threadIdx.x * 8 + r;       // 2048 odd words checked
            ok &= (w[2 * q + 1] == 0u);
        }
        int all = __syncthreads_and(ok);
        if (threadIdx.x == 0) g_is64 = all ? 1 : 0;
    }
}

// ---------------- weight prep: combined + fp16 hi/lo split (runs in fork) ----
__global__ void k_prep(const float* __restrict__ Wl0, const float* __restrict__ Wr0,
                       const float* __restrict__ Wl1, const float* __restrict__ Wr1,
                       const float* __restrict__ Wl2, const float* __restrict__ Wr2) {
    int i = blockIdx.x * 256 + threadIdx.x;
    float v;
    __half* hd;
    __half* ld;
    int idx;
    if (i < 8192) {
        int k = i / 128, c = i % 128;
        v = (c < 64) ? Wl0[k * 64 + c] : Wr0[k * 64 + (c - 64)];
        hd = g_w0h; ld = g_w0l; idx = i;
    } else if (i < 16384) {
        int j = i - 8192;
        int k = j / 128, c = j % 128;
        v = (c < 64) ? Wl1[k * 64 + c] : Wr1[k * 64 + (c - 64)];
        hd = g_w1h; ld = g_w1l; idx = j;
    } else if (i < 21504) {
        int j = i - 16384;
        int k = j / 80, c = j % 80;
        v = (c < 40) ? Wl2[k * 40 + c] : Wr2[k * 40 + (c - 40)];
        hd = g_w2h; ld = g_w2l; idx = j;
    } else {
        return;
    }
    __half h = __float2half_rn(v);
    hd[idx] = h;
    ld[idx] = __float2half_rn(v - __half2float(h));
}

// histogram of dst (reads only the dst half of edge_index, dtype-branched)
__global__ void k_decode(const void* __restrict__ ei, int E) {
    int i = blockIdx.x * blockDim.x + threadIdx.x;
    if (i >= E) return;
    int d = g_is64 ? (int)((const long long*)ei)[E + i]
                   : ((const int*)ei)[E + i];
    atomicAdd(&g_cnt[d], 1);
}

__global__ void k_scan1(int N) {
    __shared__ int sh[256];
    int i = blockIdx.x * 256 + threadIdx.x;
    int v = (i < N) ? g_cnt[i] : 0;
    sh[threadIdx.x] = v;
    __syncthreads();
    for (int off = 1; off < 256; off <<= 1) {
        int t = (threadIdx.x >= off) ? sh[threadIdx.x - off] : 0;
        __syncthreads();
        sh[threadIdx.x] += t;
        __syncthreads();
    }
    if (i < N) g_scan[i] = sh[threadIdx.x] - v;
    if (threadIdx.x == 255) g_bsum[blockIdx.x] = sh[255];
}

// scan3 with fused block-offset reduction
__global__ void k_scan3(int N, int E, int NB) {
    __shared__ int red[256];
    __shared__ int sOff;
    int tidx = threadIdx.x;
    int part = 0;
    for (int j = tidx; j < (int)blockIdx.x; j += 256) part += g_bsum[j];
    red[tidx] = part;
    __syncthreads();
    for (int off = 128; off > 0; off >>= 1) {
        if (tidx < off) red[tidx] += red[tidx + off];
        __syncthreads();
    }
    if (tidx == 0) sOff = red[0];
    __syncthreads();
    int boff = sOff;

    int i = blockIdx.x * 256 + tidx;
    if (i < N) {
        int rs = g_scan[i] + boff;
        g_rowstart[i] = rs;
        g_cur[i] = rs;
        g_inv[i] = 1.0f / fmaxf((float)g_cnt[i], 1.0f);
    }
    if (i == N) g_rowstart[N] = E;
}

// CSR fill: reads src/dst directly from edge_index (dtype-branched)
__global__ void k_fill(const void* __restrict__ ei, int E) {
    int i = blockIdx.x * blockDim.x + threadIdx.x;
    if (i >= E) return;
    int s, d;
    if (g_is64) {
        const long long* p = (const long long*)ei;
        s = (int)p[i];
        d = (int)p[E + i];
    } else {
        const int* p = (const int*)ei;
        s = p[i];
        d = p[E + i];
    }
    int pos = atomicAdd(&g_cur[d], 1);
    g_esrc[pos] = s;
}

// ---------------- linear (tensor core, W pre-split, NT=128): ------------------
// ylh = half(f(x)@Wl), yr = f(x)@Wr + b.  f = relu(affine) when AFFINE.
// fc = Xhi@Whi + Xhi@Wlo  (W-rounding eliminated; X-rounding remains).
template <int COUT, bool AFFINE>
__global__ void __launch_bounds__((2 * COUT / 16) * 32)
k_lin(const float* __restrict__ x,
      const float* __restrict__ aff,
      const __half* __restrict__ wh,
      const __half* __restrict__ wl,
      const float* __restrict__ bias,
      __half* __restrict__ ylh,
      float* __restrict__ yr,
      int N) {
    constexpr int W  = 2 * COUT;        // 128 or 80
    constexpr int NT = 128;             // node tile (rows)
    constexpr int MT = NT / 16;         // 8 m-tiles
    constexpr int NWARP = W / 16;       // 8 or 5
    constexpr int THREADS = NWARP * 32; // 256 or 160
    constexpr int LDX = 72;             // fp16 A leading dim
    constexpr int LDW = W;              // fp16 B leading dim
    constexpr int LDC = W + 4;          // fp32 C leading dim

    extern __shared__ char smemraw[];
    __half* sXhi = (__half*)smemraw;                          // NT*LDX
    __half* sWhi = sXhi + NT * LDX;                           // CIN*W
    __half* sWlo = sWhi + CIN * W;                            // CIN*W
    float*  sC   = (float*)smemraw;                           // overlay NT*LDC

    int tid = threadIdx.x;
    int tile = blockIdx.x * NT;

    // copy pre-split weights (vectorized, no conversion math)
    {
        const uint4* srcH = (const uint4*)wh;
        const uint4* srcL = (const uint4*)wl;
        uint4* dstH = (uint4*)sWhi;
        uint4* dstL = (uint4*)sWlo;
        for (int i = tid; i < CIN * W / 8; i += THREADS) {
            dstH[i] = srcH[i];
            dstL[i] = srcL[i];
        }
    }

    // stage X rows (affine+relu fused) as fp16, zero-pad tail rows
    for (int q = tid; q < NT * (CIN / 4); q += THREADS) {
        int row = q / (CIN / 4);
        int c4  = (q % (CIN / 4)) * 4;
        int n = tile + row;
        float4 xv = make_float4(0.f, 0.f, 0.f, 0.f);
        if (n < N) {
            xv = *reinterpret_cast<const float4*>(x + (size_t)n * CIN + c4);
            if (AFFINE) {
                float4 A = *reinterpret_cast<const float4*>(aff + c4);
                float4 B = *reinterpret_cast<const float4*>(aff + 64 + c4);
                xv.x = fmaxf(fmaf(xv.x, A.x, B.x), 0.f);
                xv.y = fmaxf(fmaf(xv.y, A.y, B.y), 0.f);
                xv.z = fmaxf(fmaf(xv.z, A.z, B.z), 0.f);
                xv.w = fmaxf(fmaf(xv.w, A.w, B.w), 0.f);
            }
        }
        __half2 h0 = __floats2half2_rn(xv.x, xv.y);
        __half2 h1 = __floats2half2_rn(xv.z, xv.w);
        *reinterpret_cast<__half2*>(sXhi + row * LDX + c4)     = h0;
        *reinterpret_cast<__half2*>(sXhi + row * LDX + c4 + 2) = h1;
    }
    __syncthreads();

    // compute: warp w owns n-strip [w*16, w*16+16), all MT m-tiles
    int w = tid / 32;
    int n0 = w * 16;
    wmma::fragment<wmma::accumulator, 16, 16, 16, float> fc[MT];
#pragma unroll
    for (int m = 0; m < MT; m++) wmma::fill_fragment(fc[m], 0.0f);

#pragma unroll
    for (int k = 0; k < 4; k++) {
        wmma::fragment<wmma::matrix_b, 16, 16, 16, __half, wmma::row_major> fbhi, fblo;
        wmma::load_matrix_sync(fbhi, sWhi + (k * 16) * LDW + n0, LDW);
        wmma::load_matrix_sync(fblo, sWlo + (k * 16) * LDW + n0, LDW);
#pragma unroll
        for (int m = 0; m < MT; m++) {
            wmma::fragment<wmma::matrix_a, 16, 16, 16, __half, wmma::row_major> fahi;
            wmma::load_matrix_sync(fahi, sXhi + (m * 16) * LDX + k * 16, LDX);
            wmma::mma_sync(fc[m], fahi, fbhi, fc[m]);
            wmma::mma_sync(fc[m], fahi, fblo, fc[m]);
        }
    }

    __syncthreads();    // inputs dead; safe to overlay C
#pragma unroll
    for (int m = 0; m < MT; m++)
        wmma::store_matrix_sync(sC + (m * 16) * LDC + n0, fc[m], LDC,
                                wmma::mem_row_major);
    __syncthreads();

    // epilogue: split C into ylh (cols 0..COUT) and yr (+bias, cols COUT..W)
    for (int q = tid; q < NT * (COUT / 4); q += THREADS) {
        int row = q / (COUT / 4);
        int c4  = (q % (COUT / 4)) * 4;
        int n = tile + row;
        if (n < N) {
            const float* crow = sC + row * LDC;
            __half2 p0 = __floats2half2_rn(crow[c4 + 0], crow[c4 + 1]);
            __half2 p1 = __floats2half2_rn(crow[c4 + 2], crow[c4 + 3]);
            *reinterpret_cast<__half2*>(ylh + (size_t)n * COUT + c4)     = p0;
            *reinterpret_cast<__half2*>(ylh + (size_t)n * COUT + c4 + 2) = p1;
            float4 bv = *reinterpret_cast<const float4*>(bias + c4);
            float4 rv;
            rv.x = crow[COUT + c4 + 0] + bv.x;
            rv.y = crow[COUT + c4 + 1] + bv.y;
            rv.z = crow[COUT + c4 + 2] + bv.z;
            rv.w = crow[COUT + c4 + 3] + bv.w;
            *reinterpret_cast<float4*>(yr + (size_t)n * COUT + c4) = rv;
        }
    }
}

// ---------------- CSR gather reduce: out = invdeg * sum ylh[src] + yr ----------------
// (identical to round 11-14)
template <int COUT, bool STATS, int BLOCK>
__global__ void __launch_bounds__(BLOCK)
k_agg(const __half* __restrict__ ylh,
      const float* __restrict__ yrr,
      float* __restrict__ out,
      float* __restrict__ stats,
      int* __restrict__ arrive,
      const float* __restrict__ gamma,
      const float* __restrict__ beta,
      float* __restrict__ aff,
      float invN,
      int N) {
    constexpr int CH = COUT / 8;

    __shared__ float sSum[64];
    __shared__ float sSq[64];
    __shared__ int sLast;
    int tid = threadIdx.x;
    if (STATS) {
        if (tid < 64) { sSum[tid] = 0.0f; sSq[tid] = 0.0f; }
        __syncthreads();
    }

    int t = blockIdx.x * BLOCK + tid;
    int n = t / CH;
    int c = (t % CH) * 8;
    bool active = (n < N);

    float r[8];
#pragma unroll
    for (int k = 0; k < 8; k++) r[k] = 0.0f;

    if (active) {
        int beg = g_rowstart[n];
        int end = g_rowstart[n + 1];
        float2 a0 = make_float2(0.f, 0.f), a1 = a0, a2 = a0, a3 = a0;
#pragma unroll 2
        for (int j = beg; j < end; j++) {
            int s = __ldg(&g_esrc[j]);
            uint4 v = *reinterpret_cast<const uint4*>(ylh + (size_t)s * COUT + c);
            float2 f0 = __half22float2(*reinterpret_cast<__half2*>(&v.x));
            float2 f1 = __half22float2(*reinterpret_cast<__half2*>(&v.y));
            float2 f2 = __half22float2(*reinterpret_cast<__half2*>(&v.z));
            float2 f3 = __half22float2(*reinterpret_cast<__half2*>(&v.w));
            a0.x += f0.x; a0.y += f0.y;
            a1.x += f1.x; a1.y += f1.y;
            a2.x += f2.x; a2.y += f2.y;
            a3.x += f3.x; a3.y += f3.y;
        }
        float inv = g_inv[n];
        float4 b0 = *reinterpret_cast<const float4*>(yrr + (size_t)n * COUT + c);
        float4 b1 = *reinterpret_cast<const float4*>(yrr + (size_t)n * COUT + c + 4);
        r[0] = fmaf(a0.x, inv, b0.x);
        r[1] = fmaf(a0.y, inv, b0.y);
        r[2] = fmaf(a1.x, inv, b0.z);
        r[3] = fmaf(a1.y, inv, b0.w);
        r[4] = fmaf(a2.x, inv, b1.x);
        r[5] = fmaf(a2.y, inv, b1.y);
        r[6] = fmaf(a3.x, inv, b1.z);
        r[7] = fmaf(a3.y, inv, b1.w);
        *reinterpret_cast<float4*>(out + (size_t)n * COUT + c) =
            make_float4(r[0], r[1], r[2], r[3]);
        *reinterpret_cast<float4*>(out + (size_t)n * COUT + c + 4) =
            make_float4(r[4], r[5], r[6], r[7]);
    }

    if (STATS) {
        int lane = tid & 31;
#pragma unroll
        for (int k = 0; k < 8; k++) {
            float v = r[k];
            float q = r[k] * r[k];
            v += __shfl_xor_sync(0xFFFFFFFFu, v, 8);
            q += __shfl_xor_sync(0xFFFFFFFFu, q, 8);
            v += __shfl_xor_sync(0xFFFFFFFFu, v, 16);
            q += __shfl_xor_sync(0xFFFFFFFFu, q, 16);
            if (lane < 8) {
                atomicAdd(&sSum[c + k], v);
                atomicAdd(&sSq[c + k],  q);
            }
        }
        __syncthreads();
        if (tid < 64) {
            atomicAdd(&stats[tid],      sSum[tid]);
            atomicAdd(&stats[64 + tid], sSq[tid]);
        }
        if (tid == 0) {
            __threadfence();
            int v = atomicAdd(arrive, 1);
            sLast = (v == (int)gridDim.x - 1);
        }
        __syncthreads();
        if (sLast) {
            __threadfence();
            if (tid < 64) {
                float mu  = stats[tid] * invN;
                float var = stats[64 + tid] * invN - mu * mu;
                float a = gamma[tid] * rsqrtf(var + 1e-5f);
                aff[tid] = a;
                aff[64 + tid] = beta[tid] - mu * a;
            }
        }
    }
}

// ---------------- launch ----------------
extern "C" void kernel_launch(void* const* d_in, const int* in_sizes, int n_in,
                              void* d_out, int out_size) {
    const float* x   = (const float*)d_in[0];
    const void*  ei  = d_in[1];
    const float* Wl0 = (const float*)d_in[2];
    const float* Wr0 = (const float*)d_in[3];
    const float* b0  = (const float*)d_in[4];
    const float* Wl1 = (const float*)d_in[5];
    const float* Wr1 = (const float*)d_in[6];
    const float* b1  = (const float*)d_in[7];
    const float* Wl2 = (const float*)d_in[8];
    const float* Wr2 = (const float*)d_in[9];
    const float* b2  = (const float*)d_in[10];
    const float* g0  = (const float*)d_in[11];
    const float* be0 = (const float*)d_in[12];
    const float* g1  = (const float*)d_in[13];
    const float* be1 = (const float*)d_in[14];
    float* out = (float*)d_out;

    int N = in_sizes[0] / 64;
    int E = in_sizes[1] / 2;
    float invN = 1.0f / (float)N;

    __half *ylhp, *w0hp, *w0lp, *w1hp, *w1lp, *w2hp, *w2lp;
    float *yrp, *h0p, *h1p, *aff0p, *aff1p, *st0p, *st1p;
    int *ar0p, *ar1p;
    cudaGetSymbolAddress((void**)&ylhp, g_ylh);
    cudaGetSymbolAddress((void**)&w0hp, g_w0h);
    cudaGetSymbolAddress((void**)&w0lp, g_w0l);
    cudaGetSymbolAddress((void**)&w1hp, g_w1h);
    cudaGetSymbolAddress((void**)&w1lp, g_w1l);
    cudaGetSymbolAddress((void**)&w2hp, g_w2h);
    cudaGetSymbolAddress((void**)&w2lp, g_w2l);
    cudaGetSymbolAddress((void**)&yrp, g_yr);
    cudaGetSymbolAddress((void**)&h0p, g_h0);
    cudaGetSymbolAddress((void**)&h1p, g_h1);
    cudaGetSymbolAddress((void**)&aff0p, g_aff0);
    cudaGetSymbolAddress((void**)&aff1p, g_aff1);
    cudaGetSymbolAddress((void**)&st0p, g_stats0);
    cudaGetSymbolAddress((void**)&st1p, g_stats1);
    cudaGetSymbolAddress((void**)&ar0p, g_arr0);
    cudaGetSymbolAddress((void**)&ar1p, g_arr1);

    // smem: max(load phase, C overlay phase), NT=128
    const int smem64 = 128 * 132 * 4;                          // 67584 (overlay max)
    const int smem40 = (128 * 72 + 2 * 64 * 80) * 2;           // 38912 vs 43008 overlay
    const int smem40f = 128 * 84 * 4 > smem40 ? 128 * 84 * 4 : smem40;
    cudaFuncSetAttribute(k_lin<64, false>,
                         cudaFuncAttributeMaxDynamicSharedMemorySize, smem64);
    cudaFuncSetAttribute(k_lin<64, true>,
                         cudaFuncAttributeMaxDynamicSharedMemorySize, smem64);
    cudaFuncSetAttribute(k_lin<40, true>,
                         cudaFuncAttributeMaxDynamicSharedMemorySize, smem40f);

    static cudaStream_t s2 = nullptr;
    static cudaEvent_t evFork = nullptr, evJoin = nullptr;
    if (s2 == nullptr) {
        cudaStreamCreateWithFlags(&s2, cudaStreamNonBlocking);
        cudaEventCreateWithFlags(&evFork, cudaEventDisableTiming);
        cudaEventCreateWithFlags(&evJoin, cudaEventDisableTiming);
    }

    const int nodeBlocks  = (N + 255) / 256;
    const int nodeBlocks1 = (N + 256) / 256;
    const int edgeBlocks  = (E + 255) / 256;
    const int NB          = (N + 255) / 256;
    const int agg64Blocks = (N * 8 + 255) / 256;
    const int agg40Blocks = (N * 5 + 319) / 320;
    const int mmGrid      = (N + 127) / 128;

    // fork: weight prep + lin0 run on s2, concurrent with the CSR chain
    cudaEventRecord(evFork, 0);
    cudaStreamWaitEvent(s2, evFork, 0);

    k_zero<<<nodeBlocks, 256>>>((const unsigned int*)ei, N);   // 0
    k_decode<<<edgeBlocks, 256>>>(ei, E);                      // 1
    k_prep<<<84, 256, 0, s2>>>(Wl0, Wr0, Wl1, Wr1, Wl2, Wr2);  // 2 (s2)
    k_lin<64, false><<<mmGrid, 256, smem64, s2>>>(x, nullptr,  // 3 (s2, ncu slot)
                                                  w0hp, w0lp, b0, ylhp, yrp, N);
    cudaEventRecord(evJoin, s2);
    k_scan1<<<NB, 256>>>(N);                                   // 4
    k_scan3<<<nodeBlocks1, 256>>>(N, E, NB);                   // 5
    k_fill<<<edgeBlocks, 256>>>(ei, E);                        // 6

    // ---- join, then the serial layer pipeline ----
    cudaStreamWaitEvent(0, evJoin, 0);

    // layer 0 (agg's last block computes aff0)
    k_agg<64, true, 256><<<agg64Blocks, 256>>>(ylhp, yrp, h0p, st0p, ar0p,
                                               g0, be0, aff0p, invN, N);

    // layer 1
    k_lin<64, true><<<mmGrid, 256, smem64>>>(h0p, aff0p, w1hp, w1lp, b1, ylhp, yrp, N);
    k_agg<64, true, 256><<<agg64Blocks, 256>>>(ylhp, yrp, h1p, st1p, ar1p,
                                               g1, be1, aff1p, invN, N);

    // layer 2
    k_lin<40, true><<<mmGrid, 160, smem40f>>>(h1p, aff1p, w2hp, w2lp, b2, ylhp, yrp, N);
    k_agg<40, false, 320><<<agg40Blocks, 320>>>(ylhp, yrp, out, nullptr, nullptr,
                                                nullptr, nullptr, nullptr, 0.f, N);
}

// round 16
// speedup vs baseline: 1.3686x; 1.3686x over previous
#include <cuda_runtime.h>
#include <cuda_fp16.h>
#include <mma.h>
#include <math.h>

using namespace nvcuda;

#define NMAX 100000
#define EMAX 1600000
#define CIN  64

// ---------------- device scratch (no allocation allowed) ----------------
__device__ int   g_is64;
__device__ int   g_esrc[EMAX];          // CSR: src ids sorted by dst
__device__ int   g_cnt[NMAX];
__device__ int   g_scan[NMAX];
__device__ int   g_bsum[512];
__device__ int   g_rowstart[NMAX + 1];
__device__ int   g_cur[NMAX];
__device__ float g_inv[NMAX];
__device__ __align__(256) __half g_ylh[(size_t)NMAX * 64];   // fp16 gather payload
__device__ __align__(256) float  g_yr[(size_t)NMAX * 64];
__device__ __align__(256) float  g_h0[(size_t)NMAX * 64];
__device__ __align__(256) float  g_h1[(size_t)NMAX * 64];
__device__ float g_stats0[128];         // layer0 [sum(64) | sumsq(64)]
__device__ float g_stats1[128];         // layer1
__device__ int   g_arr0;                // arrival counters (last-block bn finalize)
__device__ int   g_arr1;
__device__ float g_aff0[128];           // [scale | shift]
__device__ float g_aff1[128];

// ---------------- dtype detection (int64 vs int32 edge_index) ----------------
__global__ void k_detect(const unsigned int* __restrict__ w) {
    int i = threadIdx.x;
    int ok = (w[2 * i + 1] == 0u) && (w[2 * (i + 1024) + 1] == 0u);
    int all = __syncthreads_and(ok);
    if (i == 0) g_is64 = all ? 1 : 0;
}

// zero cnt + stats + arrival counters in one kernel
__global__ void k_zero(int N) {
    int i = blockIdx.x * blockDim.x + threadIdx.x;
    if (i < N) g_cnt[i] = 0;
    if (blockIdx.x == 0) {
        if (threadIdx.x < 128) { g_stats0[threadIdx.x] = 0.0f; g_stats1[threadIdx.x] = 0.0f; }
        if (threadIdx.x == 0) { g_arr0 = 0; g_arr1 = 0; }
    }
}

// histogram of dst (reads only the dst half of edge_index, dtype-branched)
__global__ void k_decode(const void* __restrict__ ei, int E) {
    int i = blockIdx.x * blockDim.x + threadIdx.x;
    if (i >= E) return;
    int d = g_is64 ? (int)((const long long*)ei)[E + i]
                   : ((const int*)ei)[E + i];
    atomicAdd(&g_cnt[d], 1);
}

__global__ void k_scan1(int N) {
    __shared__ int sh[256];
    int i = blockIdx.x * 256 + threadIdx.x;
    int v = (i < N) ? g_cnt[i] : 0;
    sh[threadIdx.x] = v;
    __syncthreads();
    for (int off = 1; off < 256; off <<= 1) {
        int t = (threadIdx.x >= off) ? sh[threadIdx.x - off] : 0;
        __syncthreads();
        sh[threadIdx.x] += t;
        __syncthreads();
    }
    if (i < N) g_scan[i] = sh[threadIdx.x] - v;
    if (threadIdx.x == 255) g_bsum[blockIdx.x] = sh[255];
}

// scan3 with fused block-offset reduction
__global__ void k_scan3(int N, int E, int NB) {
    __shared__ int red[256];
    __shared__ int sOff;
    int tidx = threadIdx.x;
    int part = 0;
    for (int j = tidx; j < (int)blockIdx.x; j += 256) part += g_bsum[j];
    red[tidx] = part;
    __syncthreads();
    for (int off = 128; off > 0; off >>= 1) {
        if (tidx < off) red[tidx] += red[tidx + off];
        __syncthreads();
    }
    if (tidx == 0) sOff = red[0];
    __syncthreads();
    int boff = sOff;

    int i = blockIdx.x * 256 + tidx;
    if (i < N) {
        int rs = g_scan[i] + boff;
        g_rowstart[i] = rs;
        g_cur[i] = rs;
        g_inv[i] = 1.0f / fmaxf((float)g_cnt[i], 1.0f);
    }
    if (i == N) g_rowstart[N] = E;
}

// CSR fill: reads src/dst directly from edge_index (dtype-branched)
__global__ void k_fill(const void* __restrict__ ei, int E) {
    int i = blockIdx.x * blockDim.x + threadIdx.x;
    if (i >= E) return;
    int s, d;
    if (g_is64) {
        const long long* p = (const long long*)ei;
        s = (int)p[i];
        d = (int)p[E + i];
    } else {
        const int* p = (const int*)ei;
        s = p[i];
        d = p[E + i];
    }
    int pos = atomicAdd(&g_cur[d], 1);
    g_esrc[pos] = s;
}

// ---------------- linear (tensor core, W-split only, NT=128): -----------------
// ylh = half(f(x)@Wl), yr = f(x)@Wr + b.  f = relu(affine) when AFFINE.
// fc = Xhi@Whi + Xhi@Wlo  (W-rounding eliminated in-block; X-rounding remains).
template <int COUT, bool AFFINE>
__global__ void __launch_bounds__((2 * COUT / 16) * 32)
k_lin(const float* __restrict__ x,
      const float* __restrict__ aff,
      const float* __restrict__ Wl,
      const float* __restrict__ Wr,
      const float* __restrict__ bias,
      __half* __restrict__ ylh,
      float* __restrict__ yr,
      int N) {
    constexpr int W  = 2 * COUT;        // 128 or 80
    constexpr int NT = 128;             // node tile (rows)
    constexpr int MT = NT / 16;         // 8 m-tiles
    constexpr int NWARP = W / 16;       // 8 or 5
    constexpr int THREADS = NWARP * 32; // 256 or 160
    constexpr int LDX = 72;             // fp16 A leading dim
    constexpr int LDW = W;              // fp16 B leading dim
    constexpr int LDC = W + 4;          // fp32 C leading dim

    extern __shared__ char smemraw[];
    __half* sXhi = (__half*)smemraw;                          // NT*LDX
    __half* sWhi = sXhi + NT * LDX;                           // CIN*W
    __half* sWlo = sWhi + CIN * W;                            // CIN*W
    float*  sC   = (float*)smemraw;                           // overlay NT*LDC

    int tid = threadIdx.x;
    int tile = blockIdx.x * NT;

    // stage combined weights (hi/lo split, in-block conversion)
    for (int i = tid; i < CIN * W; i += THREADS) {
        int k = i / W;
        int c = i % W;
        float v = (c < COUT) ? Wl[k * COUT + c] : Wr[k * COUT + (c - COUT)];
        __half h = __float2half_rn(v);
        sWhi[i] = h;
        sWlo[i] = __float2half_rn(v - __half2float(h));
    }

    // stage X rows (affine+relu fused) as fp16 (no split), zero-pad tail rows
    for (int q = tid; q < NT * (CIN / 4); q += THREADS) {
        int row = q / (CIN / 4);
        int c4  = (q % (CIN / 4)) * 4;
        int n = tile + row;
        float4 xv = make_float4(0.f, 0.f, 0.f, 0.f);
        if (n < N) {
            xv = *reinterpret_cast<const float4*>(x + (size_t)n * CIN + c4);
            if (AFFINE) {
                float4 A = *reinterpret_cast<const float4*>(aff + c4);
                float4 B = *reinterpret_cast<const float4*>(aff + 64 + c4);
                xv.x = fmaxf(fmaf(xv.x, A.x, B.x), 0.f);
                xv.y = fmaxf(fmaf(xv.y, A.y, B.y), 0.f);
                xv.z = fmaxf(fmaf(xv.z, A.z, B.z), 0.f);
                xv.w = fmaxf(fmaf(xv.w, A.w, B.w), 0.f);
            }
        }
        __half2 h0 = __floats2half2_rn(xv.x, xv.y);
        __half2 h1 = __floats2half2_rn(xv.z, xv.w);
        *reinterpret_cast<__half2*>(sXhi + row * LDX + c4)     = h0;
        *reinterpret_cast<__half2*>(sXhi + row * LDX + c4 + 2) = h1;
    }
    __syncthreads();

    // compute: warp w owns n-strip [w*16, w*16+16), all MT m-tiles
    int w = tid / 32;
    int n0 = w * 16;
    wmma::fragment<wmma::accumulator, 16, 16, 16, float> fc[MT];
#pragma unroll
    for (int m = 0; m < MT; m++) wmma::fill_fragment(fc[m], 0.0f);

#pragma unroll
    for (int k = 0; k < 4; k++) {
        wmma::fragment<wmma::matrix_b, 16, 16, 16, __half, wmma::row_major> fbhi, fblo;
        wmma::load_matrix_sync(fbhi, sWhi + (k * 16) * LDW + n0, LDW);
        wmma::load_matrix_sync(fblo, sWlo + (k * 16) * LDW + n0, LDW);
#pragma unroll
        for (int m = 0; m < MT; m++) {
            wmma::fragment<wmma::matrix_a, 16, 16, 16, __half, wmma::row_major> fahi;
            wmma::load_matrix_sync(fahi, sXhi + (m * 16) * LDX + k * 16, LDX);
            wmma::mma_sync(fc[m], fahi, fbhi, fc[m]);
            wmma::mma_sync(fc[m], fahi, fblo, fc[m]);
        }
    }

    __syncthreads();    // inputs dead; safe to overlay C
#pragma unroll
    for (int m = 0; m < MT; m++)
        wmma::store_matrix_sync(sC + (m * 16) * LDC + n0, fc[m], LDC,
                                wmma::mem_row_major);
    __syncthreads();

    // epilogue: split C into ylh (cols 0..COUT) and yr (+bias, cols COUT..W)
    for (int q = tid; q < NT * (COUT / 4); q += THREADS) {
        int row = q / (COUT / 4);
        int c4  = (q % (COUT / 4)) * 4;
        int n = tile + row;
        if (n < N) {
            const float* crow = sC + row * LDC;
            __half2 p0 = __floats2half2_rn(crow[c4 + 0], crow[c4 + 1]);
            __half2 p1 = __floats2half2_rn(crow[c4 + 2], crow[c4 + 3]);
            *reinterpret_cast<__half2*>(ylh + (size_t)n * COUT + c4)     = p0;
            *reinterpret_cast<__half2*>(ylh + (size_t)n * COUT + c4 + 2) = p1;
            float4 bv = *reinterpret_cast<const float4*>(bias + c4);
            float4 rv;
            rv.x = crow[COUT + c4 + 0] + bv.x;
            rv.y = crow[COUT + c4 + 1] + bv.y;
            rv.z = crow[COUT + c4 + 2] + bv.z;
            rv.w = crow[COUT + c4 + 3] + bv.w;
            *reinterpret_cast<float4*>(yr + (size_t)n * COUT + c4) = rv;
        }
    }
}

// ---------------- CSR gather reduce: out = invdeg * sum ylh[src] + yr ----------------
// (identical to round 11-14)
template <int COUT, bool STATS, int BLOCK>
__global__ void __launch_bounds__(BLOCK)
k_agg(const __half* __restrict__ ylh,
      const float* __restrict__ yrr,
      float* __restrict__ out,
      float* __restrict__ stats,
      int* __restrict__ arrive,
      const float* __restrict__ gamma,
      const float* __restrict__ beta,
      float* __restrict__ aff,
      float invN,
      int N) {
    constexpr int CH = COUT / 8;

    __shared__ float sSum[64];
    __shared__ float sSq[64];
    __shared__ int sLast;
    int tid = threadIdx.x;
    if (STATS) {
        if (tid < 64) { sSum[tid] = 0.0f; sSq[tid] = 0.0f; }
        __syncthreads();
    }

    int t = blockIdx.x * BLOCK + tid;
    int n = t / CH;
    int c = (t % CH) * 8;
    bool active = (n < N);

    float r[8];
#pragma unroll
    for (int k = 0; k < 8; k++) r[k] = 0.0f;

    if (active) {
        int beg = g_rowstart[n];
        int end = g_rowstart[n + 1];
        float2 a0 = make_float2(0.f, 0.f), a1 = a0, a2 = a0, a3 = a0;
#pragma unroll 2
        for (int j = beg; j < end; j++) {
            int s = __ldg(&g_esrc[j]);
            uint4 v = *reinterpret_cast<const uint4*>(ylh + (size_t)s * COUT + c);
            float2 f0 = __half22float2(*reinterpret_cast<__half2*>(&v.x));
            float2 f1 = __half22float2(*reinterpret_cast<__half2*>(&v.y));
            float2 f2 = __half22float2(*reinterpret_cast<__half2*>(&v.z));
            float2 f3 = __half22float2(*reinterpret_cast<__half2*>(&v.w));
            a0.x += f0.x; a0.y += f0.y;
            a1.x += f1.x; a1.y += f1.y;
            a2.x += f2.x; a2.y += f2.y;
            a3.x += f3.x; a3.y += f3.y;
        }
        float inv = g_inv[n];
        float4 b0 = *reinterpret_cast<const float4*>(yrr + (size_t)n * COUT + c);
        float4 b1 = *reinterpret_cast<const float4*>(yrr + (size_t)n * COUT + c + 4);
        r[0] = fmaf(a0.x, inv, b0.x);
        r[1] = fmaf(a0.y, inv, b0.y);
        r[2] = fmaf(a1.x, inv, b0.z);
        r[3] = fmaf(a1.y, inv, b0.w);
        r[4] = fmaf(a2.x, inv, b1.x);
        r[5] = fmaf(a2.y, inv, b1.y);
        r[6] = fmaf(a3.x, inv, b1.z);
        r[7] = fmaf(a3.y, inv, b1.w);
        *reinterpret_cast<float4*>(out + (size_t)n * COUT + c) =
            make_float4(r[0], r[1], r[2], r[3]);
        *reinterpret_cast<float4*>(out + (size_t)n * COUT + c + 4) =
            make_float4(r[4], r[5], r[6], r[7]);
    }

    if (STATS) {
        int lane = tid & 31;
#pragma unroll
        for (int k = 0; k < 8; k++) {
            float v = r[k];
            float q = r[k] * r[k];
            v += __shfl_xor_sync(0xFFFFFFFFu, v, 8);
            q += __shfl_xor_sync(0xFFFFFFFFu, q, 8);
            v += __shfl_xor_sync(0xFFFFFFFFu, v, 16);
            q += __shfl_xor_sync(0xFFFFFFFFu, q, 16);
            if (lane < 8) {
                atomicAdd(&sSum[c + k], v);
                atomicAdd(&sSq[c + k],  q);
            }
        }
        __syncthreads();
        if (tid < 64) {
            atomicAdd(&stats[tid],      sSum[tid]);
            atomicAdd(&stats[64 + tid], sSq[tid]);
        }
        if (tid == 0) {
            __threadfence();
            int v = atomicAdd(arrive, 1);
            sLast = (v == (int)gridDim.x - 1);
        }
        __syncthreads();
        if (sLast) {
            __threadfence();
            if (tid < 64) {
                float mu  = stats[tid] * invN;
                float var = stats[64 + tid] * invN - mu * mu;
                float a = gamma[tid] * rsqrtf(var + 1e-5f);
                aff[tid] = a;
                aff[64 + tid] = beta[tid] - mu * a;
            }
        }
    }
}

// ---------------- launch ----------------
extern "C" void kernel_launch(void* const* d_in, const int* in_sizes, int n_in,
                              void* d_out, int out_size) {
    const float* x   = (const float*)d_in[0];
    const void*  ei  = d_in[1];
    const float* Wl0 = (const float*)d_in[2];
    const float* Wr0 = (const float*)d_in[3];
    const float* b0  = (const float*)d_in[4];
    const float* Wl1 = (const float*)d_in[5];
    const float* Wr1 = (const float*)d_in[6];
    const float* b1  = (const float*)d_in[7];
    const float* Wl2 = (const float*)d_in[8];
    const float* Wr2 = (const float*)d_in[9];
    const float* b2  = (const float*)d_in[10];
    const float* g0  = (const float*)d_in[11];
    const float* be0 = (const float*)d_in[12];
    const float* g1  = (const float*)d_in[13];
    const float* be1 = (const float*)d_in[14];
    float* out = (float*)d_out;

    int N = in_sizes[0] / 64;
    int E = in_sizes[1] / 2;
    float invN = 1.0f / (float)N;

    __half* ylhp;
    float *yrp, *h0p, *h1p, *aff0p, *aff1p, *st0p, *st1p;
    int *ar0p, *ar1p;
    cudaGetSymbolAddress((void**)&ylhp, g_ylh);
    cudaGetSymbolAddress((void**)&yrp, g_yr);
    cudaGetSymbolAddress((void**)&h0p, g_h0);
    cudaGetSymbolAddress((void**)&h1p, g_h1);
    cudaGetSymbolAddress((void**)&aff0p, g_aff0);
    cudaGetSymbolAddress((void**)&aff1p, g_aff1);
    cudaGetSymbolAddress((void**)&st0p, g_stats0);
    cudaGetSymbolAddress((void**)&st1p, g_stats1);
    cudaGetSymbolAddress((void**)&ar0p, g_arr0);
    cudaGetSymbolAddress((void**)&ar1p, g_arr1);

    // smem: max(load phase, C overlay phase), NT=128
    // load64: 128*72*2 + 2*64*128*2 = 51200 ; overlay64: 128*132*4 = 67584
    const int smem64 = 128 * 132 * 4;                          // 67584
    // load40: 128*72*2 + 2*64*80*2 = 38912 ; overlay40: 128*84*4 = 43008
    const int smem40 = 128 * 84 * 4;                           // 43008
    cudaFuncSetAttribute(k_lin<64, false>,
                         cudaFuncAttributeMaxDynamicSharedMemorySize, smem64);
    cudaFuncSetAttribute(k_lin<64, true>,
                         cudaFuncAttributeMaxDynamicSharedMemorySize, smem64);
    cudaFuncSetAttribute(k_lin<40, true>,
                         cudaFuncAttributeMaxDynamicSharedMemorySize, smem40);

    static cudaStream_t s2 = nullptr;
    static cudaEvent_t evFork = nullptr, evJoin = nullptr;
    if (s2 == nullptr) {
        cudaStreamCreateWithFlags(&s2, cudaStreamNonBlocking);
        cudaEventCreateWithFlags(&evFork, cudaEventDisableTiming);
        cudaEventCreateWithFlags(&evJoin, cudaEventDisableTiming);
    }

    const int nodeBlocks  = (N + 255) / 256;
    const int nodeBlocks1 = (N + 256) / 256;
    const int edgeBlocks  = (E + 255) / 256;
    const int NB          = (N + 255) / 256;
    const int agg64Blocks = (N * 8 + 255) / 256;
    const int agg40Blocks = (N * 5 + 319) / 320;
    const int mmGrid      = (N + 127) / 128;

    // fork event first: s2's lin0 runs concurrently with the CSR chain.
    cudaEventRecord(evFork, 0);
    cudaStreamWaitEvent(s2, evFork, 0);

    // ---- main stream: CSR build; lin0 submitted at index 3 (ncu profile slot) ----
    k_detect<<<1, 1024>>>((const unsigned int*)ei);            // 0
    k_zero<<<nodeBlocks, 256>>>(N);                            // 1
    k_decode<<<edgeBlocks, 256>>>(ei, E);                      // 2
    k_lin<64, false><<<mmGrid, 256, smem64, s2>>>(x, nullptr,  // 3 (s2)
                                                  Wl0, Wr0, b0, ylhp, yrp, N);
    cudaEventRecord(evJoin, s2);
    k_scan1<<<NB, 256>>>(N);                                   // 4
    k_scan3<<<nodeBlocks1, 256>>>(N, E, NB);                   // 5
    k_fill<<<edgeBlocks, 256>>>(ei, E);                        // 6

    // ---- join, then the serial layer pipeline ----
    cudaStreamWaitEvent(0, evJoin, 0);

    // layer 0 (agg's last block computes aff0)
    k_agg<64, true, 256><<<agg64Blocks, 256>>>(ylhp, yrp, h0p, st0p, ar0p,
                                               g0, be0, aff0p, invN, N);

    // layer 1
    k_lin<64, true><<<mmGrid, 256, smem64>>>(h0p, aff0p, Wl1, Wr1, b1, ylhp, yrp, N);
    k_agg<64, true, 256><<<agg64Blocks, 256>>>(ylhp, yrp, h1p, st1p, ar1p,
                                               g1, be1, aff1p, invN, N);

    // layer 2
    k_lin<40, true><<<mmGrid, 160, smem40>>>(h1p, aff1p, Wl2, Wr2, b2, ylhp, yrp, N);
    k_agg<40, false, 320><<<agg40Blocks, 320>>>(ylhp, yrp, out, nullptr, nullptr,
                                                nullptr, nullptr, nullptr, 0.f, N);
}